// round 5
// baseline (speedup 1.0000x reference)
#include <cuda_runtime.h>

// out[b,t,d] = x[b,t,d] * (sum_{k<t} x[b,k,d])
// Shapes fixed by the problem: B=8, T=4096, D=1024, fp32.

#define T_DIM 4096
#define D_DIM 1024
#define D_TILE 32              // d-lanes per block (one warp width)
#define SLICES 32              // t-slices per block
#define CHUNK  (T_DIM / SLICES) // 128 t-steps per thread

__global__ __launch_bounds__(D_TILE * SLICES, 2)
void siso_scan_mul_kernel(const float* __restrict__ x, float* __restrict__ out) {
    __shared__ float ssum[SLICES][D_TILE + 1]; // +1 pad: conflict-free column reads

    const int lane_d = threadIdx.x & (D_TILE - 1);
    const int slice  = threadIdx.x >> 5;

    const int d_tiles = D_DIM / D_TILE;            // 32
    const int d_tile  = blockIdx.x & (d_tiles - 1);
    const int b       = blockIdx.x / d_tiles;

    const unsigned base =
        (unsigned)b * (T_DIM * D_DIM) + (unsigned)d_tile * D_TILE + (unsigned)lane_d;
    const unsigned t0 = (unsigned)slice * CHUNK;

    const float* __restrict__ p = x   + base + t0 * D_DIM;
    float*       __restrict__ q = out + base + t0 * D_DIM;

    // Phase 1: per-thread chunk sum. Loads are independent -> deep MLP.
    float s = 0.f;
    #pragma unroll 8
    for (int i = 0; i < CHUNK; ++i) {
        s += p[(unsigned)i * D_DIM];
    }

    ssum[slice][lane_d] = s;
    __syncthreads();

    // Phase 2: exclusive scan of the 32 chunk sums for this d-lane.
    // slice is uniform across each warp -> no divergence; padded smem -> no conflicts.
    float run = 0.f;
    for (int j = 0; j < slice; ++j) {
        run += ssum[j][lane_d];
    }

    // Phase 3: reread chunk (expected L2-resident), multiply by running prefix, store.
    #pragma unroll 8
    for (int i = 0; i < CHUNK; ++i) {
        float v = p[(unsigned)i * D_DIM];
        q[(unsigned)i * D_DIM] = v * run;
        run += v;
    }
}

extern "C" void kernel_launch(void* const* d_in, const int* in_sizes, int n_in,
                              void* d_out, int out_size) {
    const float* x = (const float*)d_in[0];
    float* out = (float*)d_out;

    const int n = in_sizes[0];                 // B*T*D = 33554432
    const int B = n / (T_DIM * D_DIM);         // 8
    const int blocks = B * (D_DIM / D_TILE);   // 256

    siso_scan_mul_kernel<<<blocks, D_TILE * SLICES>>>(x, out);
}